// round 1
// baseline (speedup 1.0000x reference)
#include <cuda_runtime.h>
#include <math.h>

#define DIMC 1024
#define NH 16
#define HD 64
#define BATCH 4
#define SEQ 2048
#define MROWS (BATCH*SEQ)   // 8192

// Scratch (device globals — no runtime allocation)
__device__ float g_q[(size_t)BATCH*NH*SEQ*HD];   // [B,H,T,D]
__device__ float g_k[(size_t)BATCH*NH*SEQ*HD];
__device__ float g_v[(size_t)BATCH*NH*SEQ*HD];
__device__ float g_o[(size_t)BATCH*SEQ*DIMC];    // [B,T,C]

// ---------------------------------------------------------------------------
// SGEMM: C[M,N] = A[M,K] @ B[K,N] + bias[N]
// BM=BN=128, BK=8, 256 threads, 8x8 per-thread microtile.
// SCATTER=1: route columns into g_q/g_k/g_v with [B,H,T,D] layout.
// ---------------------------------------------------------------------------
template<int SCATTER>
__global__ __launch_bounds__(256) void sgemm_kernel(
    const float* __restrict__ A, const float* __restrict__ Bm,
    const float* __restrict__ bias, float* __restrict__ C,
    int N, int K)
{
    const int BM = 128, BN = 128, BK = 8, TM = 8, TN = 8;
    __shared__ float As[BK * BM];   // transposed: As[k][m]
    __shared__ float Bs[BK * BN];   // Bs[k][n]

    const int tid  = threadIdx.x;
    const int tCol = tid & 15;       // 0..15
    const int tRow = tid >> 4;       // 0..15
    const int mBase = blockIdx.y * BM;
    const int nBase = blockIdx.x * BN;

    const int innerRowA = tid >> 1;          // 0..127
    const int innerColA = (tid & 1) * 4;     // 0 or 4
    const int innerRowB = tid >> 5;          // 0..7
    const int innerColB = (tid & 31) * 4;    // 0..124

    const float* Aptr = A + (size_t)mBase * K;
    const float* Bptr = Bm + nBase;

    float acc[TM][TN];
    #pragma unroll
    for (int i = 0; i < TM; i++)
        #pragma unroll
        for (int j = 0; j < TN; j++) acc[i][j] = 0.0f;

    float regM[TM], regN[TN];

    for (int kt = 0; kt < K; kt += BK) {
        float4 a = *(const float4*)(Aptr + (size_t)innerRowA * K + kt + innerColA);
        As[(innerColA + 0) * BM + innerRowA] = a.x;
        As[(innerColA + 1) * BM + innerRowA] = a.y;
        As[(innerColA + 2) * BM + innerRowA] = a.z;
        As[(innerColA + 3) * BM + innerRowA] = a.w;
        *(float4*)(Bs + innerRowB * BN + innerColB) =
            *(const float4*)(Bptr + (size_t)(kt + innerRowB) * N + innerColB);
        __syncthreads();

        #pragma unroll
        for (int kk = 0; kk < BK; kk++) {
            #pragma unroll
            for (int i = 0; i < TM; i++) regM[i] = As[kk * BM + tRow * TM + i];
            #pragma unroll
            for (int j = 0; j < TN; j++) regN[j] = Bs[kk * BN + tCol * TN + j];
            #pragma unroll
            for (int i = 0; i < TM; i++)
                #pragma unroll
                for (int j = 0; j < TN; j++)
                    acc[i][j] = fmaf(regM[i], regN[j], acc[i][j]);
        }
        __syncthreads();
    }

    #pragma unroll
    for (int i = 0; i < TM; i++) {
        const int m = mBase + tRow * TM + i;
        #pragma unroll
        for (int j = 0; j < TN; j++) {
            const int n = nBase + tCol * TN + j;
            float val = acc[i][j] + bias[n];
            if (SCATTER) {
                // n in [0,3072): section 0=q, 1=k, 2=v; within: head h, dim d
                const int bb  = m >> 11;           // /SEQ
                const int tt  = m & (SEQ - 1);
                const int sec = n >> 10;
                const int c   = n & 1023;
                const int h   = c >> 6;
                const int d   = c & 63;
                float* dst = (sec == 0) ? g_q : (sec == 1) ? g_k : g_v;
                dst[(((size_t)bb * NH + h) * SEQ + tt) * HD + d] = val;
            } else {
                C[(size_t)m * N + n] = val;
            }
        }
    }
}

// ---------------------------------------------------------------------------
// Causal flash attention, fp32. One CTA per (b*h, q-tile of 64 rows).
// 256 threads as 16x16; each thread owns a 4x4 S-tile / 4x4 O-tile.
// Q,K stored d-major in smem (conflict-free); P reuses the K buffer.
// ---------------------------------------------------------------------------
__global__ __launch_bounds__(256) void flash_attn_kernel()
{
    __shared__ float QsT[HD * 64];   // [d][q]
    __shared__ float KsT[HD * 64];   // [d][k]  -> reused as Ps[q][k]
    __shared__ float Vs[64 * HD];    // [k][d]

    const int tid = threadIdx.x;
    const int tx = tid & 15;   // n/d column group
    const int ty = tid >> 4;   // q row group
    const int bh = blockIdx.y;           // 0..63
    const int bb = bh >> 4;
    const int h  = bh & 15;
    const int q0 = blockIdx.x * 64;

    const float* Qg = g_q + (size_t)bh * SEQ * HD;
    const float* Kg = g_k + (size_t)bh * SEQ * HD;
    const float* Vg = g_v + (size_t)bh * SEQ * HD;
    const float scale = 0.125f;  // 1/sqrt(64)

    // Load Q tile, transposed + pre-scaled
    for (int i = tid; i < 64 * 16; i += 256) {
        const int r  = i >> 4;
        const int c4 = (i & 15) * 4;
        float4 qv = *(const float4*)(Qg + (size_t)(q0 + r) * HD + c4);
        QsT[(c4 + 0) * 64 + r] = qv.x * scale;
        QsT[(c4 + 1) * 64 + r] = qv.y * scale;
        QsT[(c4 + 2) * 64 + r] = qv.z * scale;
        QsT[(c4 + 3) * 64 + r] = qv.w * scale;
    }

    float m_i[4], l_i[4], accO[4][4];
    #pragma unroll
    for (int r = 0; r < 4; r++) {
        m_i[r] = -1e30f; l_i[r] = 0.0f;
        #pragma unroll
        for (int c = 0; c < 4; c++) accO[r][c] = 0.0f;
    }

    const int nTiles = (q0 >> 6) + 1;
    for (int jt = 0; jt < nTiles; jt++) {
        const int k0 = jt * 64;
        __syncthreads();   // guard KsT/Vs overwrite vs previous O-accum reads
        for (int i = tid; i < 64 * 16; i += 256) {
            const int r  = i >> 4;
            const int c4 = (i & 15) * 4;
            float4 kv = *(const float4*)(Kg + (size_t)(k0 + r) * HD + c4);
            KsT[(c4 + 0) * 64 + r] = kv.x;
            KsT[(c4 + 1) * 64 + r] = kv.y;
            KsT[(c4 + 2) * 64 + r] = kv.z;
            KsT[(c4 + 3) * 64 + r] = kv.w;
            *(float4*)(Vs + r * HD + c4) =
                *(const float4*)(Vg + (size_t)(k0 + r) * HD + c4);
        }
        __syncthreads();

        // S = Q K^T (scaled)
        float s[4][4];
        #pragma unroll
        for (int r = 0; r < 4; r++)
            #pragma unroll
            for (int c = 0; c < 4; c++) s[r][c] = 0.0f;

        for (int d = 0; d < HD; d++) {
            float qr[4];
            #pragma unroll
            for (int r = 0; r < 4; r++) qr[r] = QsT[d * 64 + ty * 4 + r];
            float4 kv4 = *(float4*)&KsT[d * 64 + tx * 4];
            const float kr[4] = {kv4.x, kv4.y, kv4.z, kv4.w};
            #pragma unroll
            for (int r = 0; r < 4; r++)
                #pragma unroll
                for (int c = 0; c < 4; c++)
                    s[r][c] = fmaf(qr[r], kr[c], s[r][c]);
        }

        if (jt == nTiles - 1) {  // diagonal tile: mask ki > qi
            #pragma unroll
            for (int r = 0; r < 4; r++)
                #pragma unroll
                for (int c = 0; c < 4; c++)
                    if (tx * 4 + c > ty * 4 + r) s[r][c] = -1e30f;
        }

        // Online softmax (row reductions across the 16 tx lanes)
        #pragma unroll
        for (int r = 0; r < 4; r++) {
            float mx = fmaxf(fmaxf(s[r][0], s[r][1]), fmaxf(s[r][2], s[r][3]));
            #pragma unroll
            for (int off = 8; off >= 1; off >>= 1)
                mx = fmaxf(mx, __shfl_xor_sync(0xffffffffu, mx, off));
            const float m_new = fmaxf(m_i[r], mx);
            const float alpha = __expf(m_i[r] - m_new);
            float rs = 0.0f;
            #pragma unroll
            for (int c = 0; c < 4; c++) {
                s[r][c] = __expf(s[r][c] - m_new);
                rs += s[r][c];
            }
            #pragma unroll
            for (int off = 8; off >= 1; off >>= 1)
                rs += __shfl_xor_sync(0xffffffffu, rs, off);
            l_i[r] = l_i[r] * alpha + rs;
            m_i[r] = m_new;
            #pragma unroll
            for (int c = 0; c < 4; c++) accO[r][c] *= alpha;
        }

        __syncthreads();   // everyone done reading KsT
        #pragma unroll
        for (int r = 0; r < 4; r++)
            #pragma unroll
            for (int c = 0; c < 4; c++)
                KsT[(ty * 4 + r) * 64 + tx * 4 + c] = s[r][c];  // P tile
        __syncthreads();

        // O += P @ V
        for (int kk = 0; kk < 64; kk++) {
            float pr[4];
            #pragma unroll
            for (int r = 0; r < 4; r++) pr[r] = KsT[(ty * 4 + r) * 64 + kk];
            float4 vv = *(float4*)&Vs[kk * HD + tx * 4];
            const float vr[4] = {vv.x, vv.y, vv.z, vv.w};
            #pragma unroll
            for (int r = 0; r < 4; r++)
                #pragma unroll
                for (int c = 0; c < 4; c++)
                    accO[r][c] = fmaf(pr[r], vr[c], accO[r][c]);
        }
    }

    // Write O back as [B,T,C]
    #pragma unroll
    for (int r = 0; r < 4; r++) {
        const float inv = 1.0f / l_i[r];
        const int qrow = q0 + ty * 4 + r;
        float* dst = g_o + ((size_t)bb * SEQ + qrow) * DIMC + h * HD + tx * 4;
        #pragma unroll
        for (int c = 0; c < 4; c++) dst[c] = accO[r][c] * inv;
    }
}

// ---------------------------------------------------------------------------
extern "C" void kernel_launch(void* const* d_in, const int* in_sizes, int n_in,
                              void* d_out, int out_size)
{
    const float* x     = (const float*)d_in[0];
    const float* W_qkv = (const float*)d_in[1];
    const float* b_qkv = (const float*)d_in[2];
    const float* W_out = (const float*)d_in[3];
    const float* b_out = (const float*)d_in[4];
    float* out = (float*)d_out;

    void* o_ptr = nullptr;
    cudaGetSymbolAddress(&o_ptr, g_o);

    // 1) QKV projection + bias + scatter into [B,H,T,D]
    {
        dim3 grid((3 * DIMC) / 128, MROWS / 128);
        sgemm_kernel<1><<<grid, 256>>>(x, W_qkv, b_qkv, nullptr, 3 * DIMC, DIMC);
    }
    // 2) Causal flash attention -> g_o [B,T,C]
    {
        dim3 grid(SEQ / 64, BATCH * NH);
        flash_attn_kernel<<<grid, 256>>>();
    }
    // 3) Output projection
    {
        dim3 grid(DIMC / 128, MROWS / 128);
        sgemm_kernel<0><<<grid, 256>>>((const float*)o_ptr, W_out, b_out, out,
                                       DIMC, DIMC);
    }
}

// round 2
// speedup vs baseline: 3.4278x; 3.4278x over previous
#include <cuda_runtime.h>
#include <math.h>
#include <stdint.h>

#define DIMC 1024
#define NH 16
#define HD 64
#define BATCH 4
#define SEQ 2048
#define MROWS (BATCH*SEQ)   // 8192

// Scratch (device globals — no runtime allocation)
__device__ float g_q[(size_t)BATCH*NH*SEQ*HD];   // [B,H,T,D]
__device__ float g_k[(size_t)BATCH*NH*SEQ*HD];
__device__ float g_v[(size_t)BATCH*NH*SEQ*HD];
__device__ float g_o[(size_t)BATCH*SEQ*DIMC];    // [B,T,C]

__device__ __forceinline__ uint32_t f2tf32(float x) {
    uint32_t r;
    asm("cvt.rna.tf32.f32 %0, %1;" : "=r"(r) : "f"(x));
    return r;
}

__device__ __forceinline__ void mma8(float c[4], const uint32_t a[4], const uint32_t b[2]) {
    asm volatile(
        "mma.sync.aligned.m16n8k8.row.col.f32.tf32.tf32.f32 "
        "{%0,%1,%2,%3}, {%4,%5,%6,%7}, {%8,%9}, {%0,%1,%2,%3};\n"
        : "+f"(c[0]), "+f"(c[1]), "+f"(c[2]), "+f"(c[3])
        : "r"(a[0]), "r"(a[1]), "r"(a[2]), "r"(a[3]), "r"(b[0]), "r"(b[1]));
}

// ---------------------------------------------------------------------------
// TF32 GEMM: C[M,N] = A[M,K] @ B[K,N] + bias[N]
// CTA 128x128, BK=32, 256 threads (8 warps, 2m x 4n), warp tile 64x32.
// SCATTER=1: route columns into g_q/g_k/g_v with [B,H,T,D] layout.
// ---------------------------------------------------------------------------
template<int SCATTER>
__global__ __launch_bounds__(256) void gemm_tf32(
    const float* __restrict__ A, const float* __restrict__ Bm,
    const float* __restrict__ bias, float* __restrict__ C,
    int N, int K)
{
    __shared__ uint32_t As[128 * 36];   // [m][k], pad 4
    __shared__ uint32_t Bs[32 * 132];   // [k][n], pad 4

    const int tid  = threadIdx.x;
    const int warp = tid >> 5;
    const int lane = tid & 31;
    const int gid  = lane >> 2;
    const int tig  = lane & 3;
    const int wm   = warp & 1;    // 0..1
    const int wn   = warp >> 1;   // 0..3
    const int mBase = blockIdx.y * 128;
    const int nBase = blockIdx.x * 128;

    float acc[4][4][4];
    #pragma unroll
    for (int mt = 0; mt < 4; mt++)
        #pragma unroll
        for (int nt = 0; nt < 4; nt++)
            #pragma unroll
            for (int i = 0; i < 4; i++) acc[mt][nt][i] = 0.0f;

    for (int kt = 0; kt < K; kt += 32) {
        // Load A tile (128x32): 4 float4 per thread
        #pragma unroll
        for (int l = 0; l < 4; l++) {
            const int lin = tid + l * 256;
            const int row = lin >> 3;
            const int c4  = (lin & 7) * 4;
            float4 v = *(const float4*)(A + (size_t)(mBase + row) * K + kt + c4);
            uint4 t = make_uint4(f2tf32(v.x), f2tf32(v.y), f2tf32(v.z), f2tf32(v.w));
            *(uint4*)&As[row * 36 + c4] = t;
        }
        // Load B tile (32x128): 4 float4 per thread
        #pragma unroll
        for (int l = 0; l < 4; l++) {
            const int lin = tid + l * 256;
            const int r   = lin >> 5;
            const int c4  = (lin & 31) * 4;
            float4 v = *(const float4*)(Bm + (size_t)(kt + r) * N + nBase + c4);
            uint4 t = make_uint4(f2tf32(v.x), f2tf32(v.y), f2tf32(v.z), f2tf32(v.w));
            *(uint4*)&Bs[r * 132 + c4] = t;
        }
        __syncthreads();

        #pragma unroll
        for (int ks = 0; ks < 4; ks++) {
            const int k0 = ks * 8;
            uint32_t a[4][4], b[4][2];
            #pragma unroll
            for (int mt = 0; mt < 4; mt++) {
                const int base = (wm * 64 + mt * 16 + gid) * 36 + k0;
                a[mt][0] = As[base + tig];
                a[mt][1] = As[base + 8 * 36 + tig];
                a[mt][2] = As[base + tig + 4];
                a[mt][3] = As[base + 8 * 36 + tig + 4];
            }
            #pragma unroll
            for (int nt = 0; nt < 4; nt++) {
                const int nb = wn * 32 + nt * 8 + gid;
                b[nt][0] = Bs[(k0 + tig) * 132 + nb];
                b[nt][1] = Bs[(k0 + tig + 4) * 132 + nb];
            }
            #pragma unroll
            for (int mt = 0; mt < 4; mt++)
                #pragma unroll
                for (int nt = 0; nt < 4; nt++)
                    mma8(acc[mt][nt], a[mt], b[nt]);
        }
        __syncthreads();
    }

    // Epilogue
    #pragma unroll
    for (int mt = 0; mt < 4; mt++) {
        const int r0 = mBase + wm * 64 + mt * 16 + gid;
        #pragma unroll
        for (int nt = 0; nt < 4; nt++) {
            const int c0 = nBase + wn * 32 + nt * 8 + tig * 2;
            #pragma unroll
            for (int i = 0; i < 4; i++) {
                const int m = r0 + (i >= 2 ? 8 : 0);
                const int n = c0 + (i & 1);
                float val = acc[mt][nt][i] + bias[n];
                if (SCATTER) {
                    const int bb  = m >> 11;
                    const int tt  = m & (SEQ - 1);
                    const int sec = n >> 10;
                    const int cc  = n & 1023;
                    const int h   = cc >> 6;
                    const int d   = cc & 63;
                    float* dst = (sec == 0) ? g_q : (sec == 1) ? g_k : g_v;
                    dst[(((size_t)bb * NH + h) * SEQ + tt) * HD + d] = val;
                } else {
                    C[(size_t)m * N + n] = val;
                }
            }
        }
    }
}

// ---------------------------------------------------------------------------
// Causal flash attention, tf32 tensor cores. CTA = 128 threads (4 warps).
// BQ=64 (16 q-rows per warp), BK=64. Q fragments register-resident.
// X buffer shared between K tile and P tile; V transposed in smem.
// ---------------------------------------------------------------------------
__global__ __launch_bounds__(128) void flash_tf32()
{
    __shared__ uint32_t X[64 * 68];    // K tile [kidx][d] -> P tile [q][kidx]
    __shared__ uint32_t VsT[64 * 68];  // [d][kidx]

    const int tid  = threadIdx.x;
    const int warp = tid >> 5;
    const int lane = tid & 31;
    const int gid  = lane >> 2;
    const int tig  = lane & 3;
    const int bh = blockIdx.y;           // b*NH + h
    const int bb = bh >> 4;
    const int h  = bh & 15;
    const int q0 = blockIdx.x * 64;

    const float* Qg = g_q + (size_t)bh * SEQ * HD;
    const float* Kg = g_k + (size_t)bh * SEQ * HD;
    const float* Vg = g_v + (size_t)bh * SEQ * HD;

    // Stage Q tile into X (scaled by 1/8), then pull fragments to registers
    #pragma unroll
    for (int l = 0; l < 8; l++) {
        const int lin = tid + l * 128;
        const int row = lin >> 4;
        const int c4  = (lin & 15) * 4;
        float4 v = *(const float4*)(Qg + (size_t)(q0 + row) * HD + c4);
        uint4 t = make_uint4(f2tf32(v.x * 0.125f), f2tf32(v.y * 0.125f),
                             f2tf32(v.z * 0.125f), f2tf32(v.w * 0.125f));
        *(uint4*)&X[row * 68 + c4] = t;
    }
    __syncthreads();

    uint32_t qf[8][4];
    {
        const int rbase = (warp * 16 + gid) * 68;
        #pragma unroll
        for (int ks = 0; ks < 8; ks++) {
            const int k0 = ks * 8;
            qf[ks][0] = X[rbase + k0 + tig];
            qf[ks][1] = X[rbase + 8 * 68 + k0 + tig];
            qf[ks][2] = X[rbase + k0 + tig + 4];
            qf[ks][3] = X[rbase + 8 * 68 + k0 + tig + 4];
        }
    }

    float m0 = -1e30f, m1 = -1e30f, l0 = 0.0f, l1 = 0.0f;
    float o[8][4];
    #pragma unroll
    for (int nt = 0; nt < 8; nt++)
        #pragma unroll
        for (int i = 0; i < 4; i++) o[nt][i] = 0.0f;

    const int nTiles = (q0 >> 6) + 1;
    for (int jt = 0; jt < nTiles; jt++) {
        const int k0g = jt * 64;
        __syncthreads();  // prior PV done reading X/VsT; also guards Q-frag reads at jt=0

        // Load K -> X [kidx][d], V -> VsT [d][kidx]
        #pragma unroll
        for (int l = 0; l < 8; l++) {
            const int lin = tid + l * 128;
            const int row = lin >> 4;
            const int c4  = (lin & 15) * 4;
            float4 kv = *(const float4*)(Kg + (size_t)(k0g + row) * HD + c4);
            uint4 t = make_uint4(f2tf32(kv.x), f2tf32(kv.y), f2tf32(kv.z), f2tf32(kv.w));
            *(uint4*)&X[row * 68 + c4] = t;
            float4 vv = *(const float4*)(Vg + (size_t)(k0g + row) * HD + c4);
            VsT[(c4 + 0) * 68 + row] = f2tf32(vv.x);
            VsT[(c4 + 1) * 68 + row] = f2tf32(vv.y);
            VsT[(c4 + 2) * 68 + row] = f2tf32(vv.z);
            VsT[(c4 + 3) * 68 + row] = f2tf32(vv.w);
        }
        __syncthreads();

        // S = Q K^T
        float s[8][4];
        #pragma unroll
        for (int nt = 0; nt < 8; nt++)
            #pragma unroll
            for (int i = 0; i < 4; i++) s[nt][i] = 0.0f;

        #pragma unroll
        for (int ks = 0; ks < 8; ks++) {
            const int k0 = ks * 8;
            #pragma unroll
            for (int nt = 0; nt < 8; nt++) {
                uint32_t b[2];
                const int kb = (nt * 8 + gid) * 68 + k0 + tig;
                b[0] = X[kb];
                b[1] = X[kb + 4];
                mma8(s[nt], qf[ks], b);
            }
        }

        // Causal mask on the diagonal tile
        if (jt == nTiles - 1) {
            const int qr0 = q0 + warp * 16 + gid;
            #pragma unroll
            for (int nt = 0; nt < 8; nt++) {
                const int kc = k0g + nt * 8 + tig * 2;
                if (kc > qr0)     s[nt][0] = -1e30f;
                if (kc + 1 > qr0) s[nt][1] = -1e30f;
                if (kc > qr0 + 8)     s[nt][2] = -1e30f;
                if (kc + 1 > qr0 + 8) s[nt][3] = -1e30f;
            }
        }

        // Online softmax (rows r0=gid, r1=gid+8 within this warp's 16)
        float mx0 = -1e30f, mx1 = -1e30f;
        #pragma unroll
        for (int nt = 0; nt < 8; nt++) {
            mx0 = fmaxf(mx0, fmaxf(s[nt][0], s[nt][1]));
            mx1 = fmaxf(mx1, fmaxf(s[nt][2], s[nt][3]));
        }
        mx0 = fmaxf(mx0, __shfl_xor_sync(0xffffffffu, mx0, 1));
        mx0 = fmaxf(mx0, __shfl_xor_sync(0xffffffffu, mx0, 2));
        mx1 = fmaxf(mx1, __shfl_xor_sync(0xffffffffu, mx1, 1));
        mx1 = fmaxf(mx1, __shfl_xor_sync(0xffffffffu, mx1, 2));

        const float mn0 = fmaxf(m0, mx0);
        const float mn1 = fmaxf(m1, mx1);
        const float al0 = __expf(m0 - mn0);
        const float al1 = __expf(m1 - mn1);

        float rs0 = 0.0f, rs1 = 0.0f;
        #pragma unroll
        for (int nt = 0; nt < 8; nt++) {
            s[nt][0] = __expf(s[nt][0] - mn0);
            s[nt][1] = __expf(s[nt][1] - mn0);
            s[nt][2] = __expf(s[nt][2] - mn1);
            s[nt][3] = __expf(s[nt][3] - mn1);
            rs0 += s[nt][0] + s[nt][1];
            rs1 += s[nt][2] + s[nt][3];
        }
        rs0 += __shfl_xor_sync(0xffffffffu, rs0, 1);
        rs0 += __shfl_xor_sync(0xffffffffu, rs0, 2);
        rs1 += __shfl_xor_sync(0xffffffffu, rs1, 1);
        rs1 += __shfl_xor_sync(0xffffffffu, rs1, 2);

        l0 = l0 * al0 + rs0;
        l1 = l1 * al1 + rs1;
        m0 = mn0; m1 = mn1;

        #pragma unroll
        for (int nt = 0; nt < 8; nt++) {
            o[nt][0] *= al0; o[nt][1] *= al0;
            o[nt][2] *= al1; o[nt][3] *= al1;
        }

        __syncthreads();  // all warps done reading X as K

        // Write P tile (tf32) into X: [q][kidx]
        {
            const int r0 = (warp * 16 + gid) * 68;
            const int r1 = r0 + 8 * 68;
            #pragma unroll
            for (int nt = 0; nt < 8; nt++) {
                const int cc = nt * 8 + tig * 2;
                X[r0 + cc]     = f2tf32(s[nt][0]);
                X[r0 + cc + 1] = f2tf32(s[nt][1]);
                X[r1 + cc]     = f2tf32(s[nt][2]);
                X[r1 + cc + 1] = f2tf32(s[nt][3]);
            }
        }
        __syncwarp();  // each warp reads only its own rows of P

        // O += P @ V
        #pragma unroll
        for (int ks = 0; ks < 8; ks++) {
            const int k0 = ks * 8;
            uint32_t pa[4];
            const int rbase = (warp * 16 + gid) * 68;
            pa[0] = X[rbase + k0 + tig];
            pa[1] = X[rbase + 8 * 68 + k0 + tig];
            pa[2] = X[rbase + k0 + tig + 4];
            pa[3] = X[rbase + 8 * 68 + k0 + tig + 4];
            #pragma unroll
            for (int nt = 0; nt < 8; nt++) {
                uint32_t b[2];
                const int vb = (nt * 8 + gid) * 68 + k0 + tig;
                b[0] = VsT[vb];
                b[1] = VsT[vb + 4];
                mma8(o[nt], pa, b);
            }
        }
    }

    // Epilogue: normalize and write [B,T,C]
    const float inv0 = 1.0f / l0;
    const float inv1 = 1.0f / l1;
    const int qr0 = q0 + warp * 16 + gid;
    float* dst0 = g_o + ((size_t)bb * SEQ + qr0) * DIMC + h * HD;
    float* dst1 = g_o + ((size_t)bb * SEQ + qr0 + 8) * DIMC + h * HD;
    #pragma unroll
    for (int nt = 0; nt < 8; nt++) {
        const int d = nt * 8 + tig * 2;
        dst0[d]     = o[nt][0] * inv0;
        dst0[d + 1] = o[nt][1] * inv0;
        dst1[d]     = o[nt][2] * inv1;
        dst1[d + 1] = o[nt][3] * inv1;
    }
}

// ---------------------------------------------------------------------------
extern "C" void kernel_launch(void* const* d_in, const int* in_sizes, int n_in,
                              void* d_out, int out_size)
{
    const float* x     = (const float*)d_in[0];
    const float* W_qkv = (const float*)d_in[1];
    const float* b_qkv = (const float*)d_in[2];
    const float* W_out = (const float*)d_in[3];
    const float* b_out = (const float*)d_in[4];
    float* out = (float*)d_out;

    void* o_ptr = nullptr;
    cudaGetSymbolAddress(&o_ptr, g_o);

    // 1) QKV projection + bias + scatter into [B,H,T,D]
    {
        dim3 grid((3 * DIMC) / 128, MROWS / 128);
        gemm_tf32<1><<<grid, 256>>>(x, W_qkv, b_qkv, nullptr, 3 * DIMC, DIMC);
    }
    // 2) Causal flash attention -> g_o [B,T,C]
    {
        dim3 grid(SEQ / 64, BATCH * NH);
        flash_tf32<<<grid, 128>>>();
    }
    // 3) Output projection
    {
        dim3 grid(DIMC / 128, MROWS / 128);
        gemm_tf32<0><<<grid, 256>>>((const float*)o_ptr, W_out, b_out, out,
                                    DIMC, DIMC);
    }
}